// round 11
// baseline (speedup 1.0000x reference)
#include <cuda_runtime.h>
#include <cuda_bf16.h>

// Problem constants (fixed by the reference)
#define BATCH 16
#define MCTRL 64
#define NCTRL 64
#define DEG   3
#define LKNOT 68                // M + P + 1
#define NSPAN (LKNOT - 2*DEG)   // 62 candidate spans
#define OUTU  256
#define OUTV  256
#define U_PER 8                 // u samples per block

// Fully fused kernel. Grid: (OUTU/U_PER, BATCH) = (32,16) = 512 x 256 threads.
//
//   1. EVERY warp independently: load 68 knots (L2-hot after first block of a
//      batch), pure-shfl inclusive scan, normalize, write K[] to smem.
//      All warps write bit-identical values (same inputs, same op order), so
//      the overlapping stores are benign; each warp only needs ITS OWN writes
//      visible (__syncwarp). This removes the warp0-serialized prologue and
//      the first block-wide barrier entirely.
//      (Nu == Nv and uspan == vspan: the reference builds V from knot_u;
//       u/v linspaces + degrees are identical -> one table serves both axes.)
//   2. Each thread: compute its TWO fold tasks' u-spans (cheap binary
//      searches), immediately issue all 8 LDG.128 control-point prefetches
//      (MLP=8), THEN compute its own sample basis (binary search + one
//      Cox-de-Boor) while the loads are in flight.
//   3. The 8 threads whose sample is one of the block's u's publish their
//      basis; barrier; fold both tasks with the prefetched data; barrier.
//   4. Stage B: thread t evaluates v = t for all 8 u's, 2 u's interleaved
//      per group (8 LDS.128 in flight): 4 LDS.128 + 12 FMA + 3 streaming STG
//      per point.
//
// Span-search correctness: the reference predicate (tv - K[s+DEG]) > 1e-8 is
// prefix-true in s (K monotone non-decreasing; fp subtract with a fixed
// minuend is monotone), so argmin-with-first-tie == prefix-count - 1. The
// binary search probes the identical fp expression -> bit-equal span.
// Cox-de Boor uses __fdividef (2-ulp) -- ~1e-6 impact vs 1e-3 tolerance.

__device__ __forceinline__ int find_cnt(const float* __restrict__ K, float tv) {
    int cnt = 0;
    #pragma unroll
    for (int s = 32; s; s >>= 1) {
        const int ns = cnt + s;
        if (ns <= NSPAN && ((tv - K[ns - 1 + DEG]) > 1e-8f)) cnt = ns;
    }
    return cnt;
}

__global__ void __launch_bounds__(256) surf_kernel(const float* __restrict__ ctrl,
                                                   const float* __restrict__ knot_u,
                                                   float* __restrict__ out) {
    const int u0 = blockIdx.x * U_PER;
    const int b  = blockIdx.y;
    const int t  = threadIdx.x;

    __shared__ float  K[LKNOT];           // normalized knots (written by all warps)
    __shared__ float4 sbu[U_PER];         // basis for this block's u samples
    __shared__ float4 stmp[U_PER][NCTRL]; // u-folded rows (8 KB)

    // ---- 1. per-warp knot scan + normalize (no block barrier) -------------
    {
        const float* kn = knot_u + b * LKNOT;
        const int l = t & 31;
        float a0 = kn[l];
        float a1 = kn[l + 32];
        float a2 = (l < 4) ? kn[l + 64] : 0.f;

        #pragma unroll
        for (int off = 1; off < 32; off <<= 1) {
            const float n0 = __shfl_up_sync(0xffffffffu, a0, off);
            const float n1 = __shfl_up_sync(0xffffffffu, a1, off);
            const float n2 = __shfl_up_sync(0xffffffffu, a2, off);
            if (l >= off) { a0 += n0; a1 += n1; a2 += n2; }
        }
        const float tot0  = __shfl_sync(0xffffffffu, a0, 31);
        const float tot1  = __shfl_sync(0xffffffffu, a1, 31);
        const float cs2_3 = __shfl_sync(0xffffffffu, a2, 3);   // sum of last 4
        const float c0    = __shfl_sync(0xffffffffu, a0, 0);   // cs[0]
        const float den   = (tot0 + tot1 + cs2_3) - c0;        // cs[67]-cs[0]

        // All warps store identical bit patterns; each warp needs only its own
        // writes visible to itself (__syncwarp below).
        K[l]      = (a0 - c0) / den;
        K[l + 32] = (tot0 + a1 - c0) / den;
        if (l < 4) K[l + 64] = (tot0 + tot1 + a2 - c0) / den;
        __syncwarp();
    }

    // linspace(1e-5, 1-1e-5, 256): start + i*step, endpoint exact.
    const float start = 1e-5f;
    const float stop  = 1.0f - 1e-5f;
    const float step  = (stop - start) / (float)(OUTU - 1);

    // ---- 2a. fold-task spans (cheap) + 8-deep LDG prefetch ----------------
    const int up = t >> 6;            // 0..3  (second task: up+4)
    const int n  = t & 63;            // 0..63
    const int uA = u0 + up;
    const int uB = u0 + up + 4;

    float tA = start + (float)uA * step;
    if (uA == OUTU - 1) tA = stop;
    float tB = start + (float)uB * step;
    if (uB == OUTU - 1) tB = stop;

    const int sA = find_cnt(K, tA) - 1;    // spanA - DEG
    const int sB = find_cnt(K, tB) - 1;

    const float4* cp = reinterpret_cast<const float4*>(ctrl)
                     + (size_t)b * MCTRL * NCTRL + n;
    // All 8 loads in flight across the Cox-de-Boor math below (MLP=8).
    const float4 a0 = cp[(sA + 0) * NCTRL];
    const float4 a1 = cp[(sA + 1) * NCTRL];
    const float4 a2 = cp[(sA + 2) * NCTRL];
    const float4 a3 = cp[(sA + 3) * NCTRL];
    const float4 b0 = cp[(sB + 0) * NCTRL];
    const float4 b1 = cp[(sB + 1) * NCTRL];
    const float4 b2 = cp[(sB + 2) * NCTRL];
    const float4 b3 = cp[(sB + 3) * NCTRL];

    // ---- 2b. own-sample basis (v == t), overlapped with the LDGs ----------
    const int v = t;
    float tv = start + (float)v * step;
    if (v == OUTV - 1) tv = stop;

    const int cv   = find_cnt(K, tv);
    const int span = DEG + cv - 1;
    const int sv   = cv - 1;

    float Nb[DEG + 1];
    Nb[0] = 1.f;
    #pragma unroll
    for (int k = 1; k <= DEG; k++) {
        float saved = 0.f;
        #pragma unroll
        for (int r = 0; r < k; r++) {
            const float K1 = K[span + r + 1];
            const float K2 = K[span + 1 - k + r];
            const float denom = (K1 - tv) + (tv - K2);
            const float temp  = __fdividef(Nb[r], denom);
            Nb[r] = saved + (K1 - tv) * temp;
            saved = (tv - K2) * temp;
        }
        Nb[k] = saved;
    }

    // ---- 3. publish the block's u-bases, barrier, fold ---------------------
    {
        const unsigned du = (unsigned)(t - u0);   // thread with v == u0+du
        if (du < U_PER) sbu[du] = make_float4(Nb[0], Nb[1], Nb[2], Nb[3]);
    }
    __syncthreads();

    {
        const float4 NA = sbu[up];
        const float4 NB = sbu[up + 4];

        float4 r;
        r.x = fmaf(NA.x, a0.x, fmaf(NA.y, a1.x, fmaf(NA.z, a2.x, NA.w * a3.x)));
        r.y = fmaf(NA.x, a0.y, fmaf(NA.y, a1.y, fmaf(NA.z, a2.y, NA.w * a3.y)));
        r.z = fmaf(NA.x, a0.z, fmaf(NA.y, a1.z, fmaf(NA.z, a2.z, NA.w * a3.z)));
        r.w = 0.f;
        stmp[up][n] = r;

        float4 s;
        s.x = fmaf(NB.x, b0.x, fmaf(NB.y, b1.x, fmaf(NB.z, b2.x, NB.w * b3.x)));
        s.y = fmaf(NB.x, b0.y, fmaf(NB.y, b1.y, fmaf(NB.z, b2.y, NB.w * b3.y)));
        s.z = fmaf(NB.x, b0.z, fmaf(NB.y, b1.z, fmaf(NB.z, b2.z, NB.w * b3.z)));
        s.w = 0.f;
        stmp[up + 4][n] = s;
    }
    __syncthreads();

    // ---- 4. Stage B: per-v contraction, 2 u's interleaved ------------------
    const float nv0 = Nb[0], nv1 = Nb[1], nv2 = Nb[2], nv3 = Nb[3];

    float* op = out + (((size_t)b * OUTU + u0) * OUTV + v) * 3;

    #pragma unroll
    for (int w = 0; w < U_PER; w += 2) {
        // 8 LDS.128 issued back-to-back: latency overlapped across both u's.
        const float4 c0 = stmp[w][sv + 0];
        const float4 c1 = stmp[w][sv + 1];
        const float4 c2 = stmp[w][sv + 2];
        const float4 c3 = stmp[w][sv + 3];
        const float4 d0 = stmp[w + 1][sv + 0];
        const float4 d1 = stmp[w + 1][sv + 1];
        const float4 d2 = stmp[w + 1][sv + 2];
        const float4 d3 = stmp[w + 1][sv + 3];

        const float ax = fmaf(nv0, c0.x, fmaf(nv1, c1.x, fmaf(nv2, c2.x, nv3 * c3.x)));
        const float ay = fmaf(nv0, c0.y, fmaf(nv1, c1.y, fmaf(nv2, c2.y, nv3 * c3.y)));
        const float az = fmaf(nv0, c0.z, fmaf(nv1, c1.z, fmaf(nv2, c2.z, nv3 * c3.z)));
        const float bx = fmaf(nv0, d0.x, fmaf(nv1, d1.x, fmaf(nv2, d2.x, nv3 * d3.x)));
        const float by = fmaf(nv0, d0.y, fmaf(nv1, d1.y, fmaf(nv2, d2.y, nv3 * d3.y)));
        const float bz = fmaf(nv0, d0.z, fmaf(nv1, d1.z, fmaf(nv2, d2.z, nv3 * d3.z)));

        float* o0 = op + (size_t)w * OUTV * 3;
        float* o1 = o0 + OUTV * 3;
        __stcs(o0 + 0, ax);   // streaming: write-once output, keep out of L1
        __stcs(o0 + 1, ay);
        __stcs(o0 + 2, az);
        __stcs(o1 + 0, bx);
        __stcs(o1 + 1, by);
        __stcs(o1 + 2, bz);
    }
}

// ---------------------------------------------------------------------------
// Launch. Inputs per metadata order: ctrl_pts [16,64,64,4] f32,
// knot_u [16,68] f32, knot_v [16,68] f32 (unused — the reference builds both
// directions from knot_u).
// ---------------------------------------------------------------------------
extern "C" void kernel_launch(void* const* d_in, const int* in_sizes, int n_in,
                              void* d_out, int out_size) {
    const float* ctrl   = (const float*)d_in[0];
    const float* knot_u = (const float*)d_in[1];
    float* out = (float*)d_out;

    surf_kernel<<<dim3(OUTU / U_PER, BATCH), 256>>>(ctrl, knot_u, out);
}